// round 3
// baseline (speedup 1.0000x reference)
#include <cuda_runtime.h>

#define N_NODES 10000
#define N_EDGES 160000
#define E_HALF  80000
#define C       16
#define C2      8
#define HID     64
#define NH      2
#define NG      16
#define F_IN    64
#define F_OUT   32
#define NI      65   // intervals = HID+1
#define CP      20   // padded row for shared S tables (bank spread)

#define NODE_BLOCKS 40   // ceil(10000/256)

// ---------------- scratch (device globals; no allocations allowed) ----------
__device__ __align__(16) float g_x[N_NODES * C];                 // [n][c]
__device__ __align__(16) float g_q[N_NODES * NH * C];            // [n][h][c]
__device__ __align__(16) float g_k[N_NODES * NH * C];            // [n][h][c]
__device__ float    g_dist[N_EDGES];
__device__ __align__(8) float g_logit[N_EDGES * NH];             // [e][h]
__device__ uchar2   g_idx[N_EDGES];                              // interval idx per head
__device__ __align__(8) unsigned g_m[N_NODES * NH];              // [n][h]
__device__ __align__(8) float    g_z[N_NODES * NH];              // [n][h]
__device__ __align__(16) float g_accp[N_NODES * NH * C2];        // projected acc [n][h][j]
__device__ float    g_pooled[NG * NH * C2];

// piecewise-linear tables:  wv0[c](df) = S0[c] + df*S1[c];  bias(df) = A0 + df*A1
__device__ float g_t [NH][HID];      // sorted breakpoints
__device__ __align__(16) float g_S0[NH][NI][C];
__device__ __align__(16) float g_S1[NH][NI][C];
__device__ float g_A0[NH][NI];
__device__ float g_A1[NH][NI];

// order-preserving float<->uint encoding for atomicMax on floats
__device__ __forceinline__ unsigned fenc(float f) {
    unsigned u = __float_as_uint(f);
    return (u & 0x80000000u) ? ~u : (u | 0x80000000u);
}
__device__ __forceinline__ float fdec(unsigned u) {
    return (u & 0x80000000u) ? __uint_as_float(u & 0x7fffffffu)
                             : __uint_as_float(~u);
}
#define ENC_NEG_INF 0x007FFFFFu   // fenc(-inf)

__device__ __forceinline__ void red_v4(float* p, float4 v) {
    asm volatile("red.global.add.v4.f32 [%0], {%1, %2, %3, %4};"
                 :: "l"(p), "f"(v.x), "f"(v.y), "f"(v.z), "f"(v.w) : "memory");
}
__device__ __forceinline__ void red_f(float* p, float v) {
    asm volatile("red.global.add.f32 [%0], %1;" :: "l"(p), "f"(v) : "memory");
}

// binary search over smem breakpoints: # strictly < df, result in [0,64]
__device__ __forceinline__ int bsearch64(const float* t, float df) {
    int lo = 0, hi = HID;
#pragma unroll
    for (int it = 0; it < 7; it++) {
        if (lo < hi) {
            int mid = (lo + hi) >> 1;
            if (t[mid] < df) lo = mid + 1; else hi = mid;
        }
    }
    return lo;
}

// ---------------- kernel 1: nodes (embed+q/k+init) + table block ------------
__global__ void __launch_bounds__(256)
k_nodes(const float* __restrict__ NF,
        const float* __restrict__ We,
        const float* __restrict__ be,
        const float* __restrict__ Wq,
        const float* __restrict__ Wk,
        const float* __restrict__ W1,
        const float* __restrict__ b1,
        const float* __restrict__ Wa,
        const float* __restrict__ Wv) {
    int tid = threadIdx.x;

    if (blockIdx.x == NODE_BLOCKS) {
        // ---- table-builder block ----
        __shared__ float raw[NH][HID];
        __shared__ float stt[NH][HID];
        if (tid < NH * HID) {
            int h = tid / HID, j = tid % HID;
            float w = W1[h * HID + j], b = b1[h * HID + j];
            raw[h][j] = (w != 0.f) ? (-b / w) : -1e30f;  // w==0: park at -inf
        }
        __syncthreads();
        if (tid < NH * HID) {
            int h = tid / HID, j = tid % HID;
            float v = raw[h][j];
            int rank = 0;
            for (int i = 0; i < HID; i++) {
                float o = raw[h][i];
                rank += (o < v || (o == v && i < j)) ? 1 : 0;
            }
            stt[h][rank] = v;
            g_t[h][rank] = v;
        }
        __syncthreads();
        if (tid < NH * NI) {
            int h = tid / NI, i = tid % NI;
            float lo = (i == 0)   ? stt[h][0] - 1.0f       : stt[h][i - 1];
            float hi = (i == HID) ? stt[h][HID - 1] + 1.0f : stt[h][i];
            float mid = 0.5f * (lo + hi);
            float S0[C], S1[C], A0 = 0.f, A1 = 0.f;
#pragma unroll
            for (int c = 0; c < C; c++) { S0[c] = 0.f; S1[c] = 0.f; }
            for (int j = 0; j < HID; j++) {
                float w = W1[h * HID + j], b = b1[h * HID + j];
                if (fmaf(w, mid, b) > 0.f) {
                    float wa = Wa[h * HID + j];
                    A0 = fmaf(b, wa, A0);
                    A1 = fmaf(w, wa, A1);
#pragma unroll
                    for (int c = 0; c < C; c++) {
                        float wv = Wv[(h * HID + j) * (C * 3) + 3 * c]; // m=0 slice
                        S0[c] = fmaf(b, wv, S0[c]);
                        S1[c] = fmaf(w, wv, S1[c]);
                    }
                }
            }
#pragma unroll
            for (int c = 0; c < C; c++) { g_S0[h][i][c] = S0[c]; g_S1[h][i][c] = S1[c]; }
            g_A0[h][i] = A0; g_A1[h][i] = A1;
        }
        if (tid < NG * NH * C2) g_pooled[tid] = 0.f;
        return;
    }

    // ---- node blocks ----
    __shared__ float sWe[F_IN * C];
    __shared__ float sbe[C];
    __shared__ float sWq[NH * C * C];
    __shared__ float sWk[NH * C * C];
    for (int i = tid; i < F_IN * C; i += blockDim.x) sWe[i] = We[i];
    for (int i = tid; i < C; i += blockDim.x) sbe[i] = be[i];
    for (int i = tid; i < NH * C * C; i += blockDim.x) { sWq[i] = Wq[i]; sWk[i] = Wk[i]; }
    __syncthreads();

    int n = blockIdx.x * blockDim.x + tid;
    if (n >= N_NODES) return;

    // init per-node scratch
    *(uint2*)(g_m + n * NH) = make_uint2(ENC_NEG_INF, ENC_NEG_INF);
    *(float2*)(g_z + n * NH) = make_float2(0.f, 0.f);
    float4 zf4 = make_float4(0.f, 0.f, 0.f, 0.f);
    float4* ac = (float4*)(g_accp + n * NH * C2);
#pragma unroll
    for (int i = 0; i < 4; i++) ac[i] = zf4;

    float x[C];
#pragma unroll
    for (int j = 0; j < C; j++) x[j] = sbe[j];
    const float4* nf4 = (const float4*)(NF + n * F_IN);
#pragma unroll
    for (int i4 = 0; i4 < F_IN / 4; i4++) {
        float4 v = nf4[i4];
        float vs[4] = { v.x, v.y, v.z, v.w };
#pragma unroll
        for (int k = 0; k < 4; k++) {
            float vv = vs[k];
            int i = i4 * 4 + k;
#pragma unroll
            for (int j = 0; j < C; j++) x[j] = fmaf(vv, sWe[i * C + j], x[j]);
        }
    }
#pragma unroll
    for (int j = 0; j < C; j++) g_x[n * C + j] = x[j];

#pragma unroll
    for (int h = 0; h < NH; h++) {
        float q[C], k[C];
#pragma unroll
        for (int j = 0; j < C; j++) { q[j] = 0.f; k[j] = 0.f; }
#pragma unroll
        for (int i = 0; i < C; i++) {
            float xi = x[i];
#pragma unroll
            for (int j = 0; j < C; j++) {
                q[j] = fmaf(xi, sWq[h * C * C + i * C + j], q[j]);
                k[j] = fmaf(xi, sWk[h * C * C + i * C + j], k[j]);
            }
        }
        float* qp = g_q + (n * NH + h) * C;
        float* kp = g_k + (n * NH + h) * C;
#pragma unroll
        for (int j = 0; j < C; j++) { qp[j] = q[j]; kp[j] = k[j]; }
    }
}

// ---------------- kernel 2: edge logits + segment max (2 edges/thread) ------
__global__ void __launch_bounds__(256)
k_edge_logit(const float* __restrict__ pos,
             const int* __restrict__ ei) {
    __shared__ float  st[NH][HID];
    __shared__ float2 sA[NH][NI];
    for (int i = threadIdx.x; i < NH * HID; i += blockDim.x)
        st[i / HID][i % HID] = g_t[i / HID][i % HID];
    for (int i = threadIdx.x; i < NH * NI; i += blockDim.x)
        sA[i / NI][i % NI] = make_float2(g_A0[i / NI][i % NI], g_A1[i / NI][i % NI]);
    __syncthreads();

    int i = blockIdx.x * blockDim.x + threadIdx.x;
    if (i >= E_HALF) return;

    int e[2]  = { i, i + E_HALF };
    int s[2], t[2];
#pragma unroll
    for (int u = 0; u < 2; u++) { s[u] = ei[e[u]]; t[u] = ei[N_EDGES + e[u]]; }

    float d[2], d2i[2];
#pragma unroll
    for (int u = 0; u < 2; u++) {
        float dx = pos[3 * t[u] + 0] - pos[3 * s[u] + 0];
        float dy = pos[3 * t[u] + 1] - pos[3 * s[u] + 1];
        float dz = pos[3 * t[u] + 2] - pos[3 * s[u] + 2];
        float d2 = dx * dx + dy * dy + dz * dz;
        d[u]   = sqrtf(d2);
        d2i[u] = 1.0f / d2;
    }

#pragma unroll
    for (int u = 0; u < 2; u++) {
        float df_h[NH] = { d[u], d2i[u] };
        float2 lg2;
        uchar2 ix2;
#pragma unroll
        for (int h = 0; h < NH; h++) {
            float df = df_h[h];
            int idx = bsearch64(st[h], df);
            float2 A = sA[h][idx];
            float ab = fmaf(df, A.y, A.x);

            const float4* qt = (const float4*)(g_q + (t[u] * NH + h) * C);
            const float4* ks = (const float4*)(g_k + (s[u] * NH + h) * C);
            float dot = 0.f;
#pragma unroll
            for (int i4 = 0; i4 < 4; i4++) {
                float4 a = qt[i4], b = ks[i4];
                dot += a.x * b.x + a.y * b.y + a.z * b.z + a.w * b.w;
            }
            float lg = fmaf(dot, 0.25f, ab);   // 1/sqrt(C) = 0.25
            (h == 0 ? lg2.x : lg2.y) = lg;
            (h == 0 ? ix2.x : ix2.y) = (unsigned char)idx;
            atomicMax(&g_m[t[u] * NH + h], fenc(lg));
        }
        g_dist[e[u]] = d[u];
        *(float2*)(g_logit + e[u] * NH) = lg2;
        g_idx[e[u]] = ix2;
    }
}

// ---------------- kernel 3: exp + projected message accumulate --------------
__global__ void __launch_bounds__(256)
k_edge_acc(const int* __restrict__ ei,
           const float* __restrict__ Wo) {
    __shared__ __align__(16) float sS0[NH * NI * CP];
    __shared__ __align__(16) float sS1[NH * NI * CP];
    __shared__ float sWo[NH * C * C2];   // li=0 slice: [h][c][j]
    for (int i = threadIdx.x; i < NH * NI * (C / 4); i += blockDim.x) {
        int hi4 = i / (C / 4);           // h*NI+interval
        int c4  = i % (C / 4);
        float4 a = ((const float4*)g_S0)[i];
        float4 b = ((const float4*)g_S1)[i];
        *(float4*)(sS0 + hi4 * CP + c4 * 4) = a;
        *(float4*)(sS1 + hi4 * CP + c4 * 4) = b;
    }
    for (int i = threadIdx.x; i < NH * C * C2; i += blockDim.x) {
        int h = i / (C * C2);
        int r = i % (C * C2);
        sWo[i] = Wo[h * 3 * C * C2 + r]; // li = 0 slice
    }
    __syncthreads();

    int i = blockIdx.x * blockDim.x + threadIdx.x;
    if (i >= E_HALF) return;
    int e[2] = { i, i + E_HALF };

#pragma unroll
    for (int u = 0; u < 2; u++) {
        int s = ei[e[u]];
        int t = ei[N_EDGES + e[u]];

        float4 xs[4];
        {
            const float4* xp = (const float4*)(g_x + s * C);
#pragma unroll
            for (int i4 = 0; i4 < 4; i4++) xs[i4] = xp[i4];
        }
        float dd = g_dist[e[u]];
        float df_h[NH] = { dd, 1.0f / (dd * dd) };

        float2 lg2 = *(const float2*)(g_logit + e[u] * NH);
        uchar2 ix2 = g_idx[e[u]];
        uint2  m2  = *(const uint2*)(g_m + t * NH);
        float lg_h[NH] = { lg2.x, lg2.y };
        float m_h [NH] = { fdec(m2.x), fdec(m2.y) };
        int   ix_h[NH] = { ix2.x, ix2.y };

#pragma unroll
        for (int h = 0; h < NH; h++) {
            float ex = __expf(lg_h[h] - m_h[h]);
            red_f(&g_z[t * NH + h], ex);

            float df = df_h[h];
            const float* p0 = sS0 + (h * NI + ix_h[h]) * CP;
            const float* p1 = sS1 + (h * NI + ix_h[h]) * CP;
            float p[C2];
#pragma unroll
            for (int j = 0; j < C2; j++) p[j] = 0.f;
#pragma unroll
            for (int i4 = 0; i4 < 4; i4++) {
                float4 a = *(const float4*)(p0 + i4 * 4);
                float4 b = *(const float4*)(p1 + i4 * 4);
                float4 xv = xs[i4];
                float w0 = fmaf(df, b.x, a.x) * xv.x;
                float w1 = fmaf(df, b.y, a.y) * xv.y;
                float w2 = fmaf(df, b.z, a.z) * xv.z;
                float w3 = fmaf(df, b.w, a.w) * xv.w;
                const float* wo = sWo + h * C * C2 + (i4 * 4) * C2;
#pragma unroll
                for (int j = 0; j < C2; j++) {
                    p[j] = fmaf(w0, wo[0 * C2 + j], p[j]);
                    p[j] = fmaf(w1, wo[1 * C2 + j], p[j]);
                    p[j] = fmaf(w2, wo[2 * C2 + j], p[j]);
                    p[j] = fmaf(w3, wo[3 * C2 + j], p[j]);
                }
            }
            float* accp = g_accp + (t * NH + h) * C2;
            red_v4(accp,     make_float4(ex * p[0], ex * p[1], ex * p[2], ex * p[3]));
            red_v4(accp + 4, make_float4(ex * p[4], ex * p[5], ex * p[6], ex * p[7]));
        }
    }
}

// ---------------- kernel 4: normalize + batch pool --------------------------
__global__ void __launch_bounds__(256)
k_node_out(const int* __restrict__ batch) {
    __shared__ float sp[NG * NH * C2];
    for (int i = threadIdx.x; i < NG * NH * C2; i += blockDim.x) sp[i] = 0.f;
    __syncthreads();

    int n = blockIdx.x * blockDim.x + threadIdx.x;
    if (n < N_NODES) {
        int g = batch[n];
        float2 z2 = *(const float2*)(g_z + n * NH);
        float z_h[NH] = { z2.x, z2.y };
#pragma unroll
        for (int h = 0; h < NH; h++) {
            float z = z_h[h];
            if (z > 0.f) {
                float inv = 1.0f / z;
                const float4* ap = (const float4*)(g_accp + (n * NH + h) * C2);
                float4 a0 = ap[0], a1 = ap[1];
                float* dst = sp + (g * NH + h) * C2;
                atomicAdd(dst + 0, a0.x * inv);
                atomicAdd(dst + 1, a0.y * inv);
                atomicAdd(dst + 2, a0.z * inv);
                atomicAdd(dst + 3, a0.w * inv);
                atomicAdd(dst + 4, a1.x * inv);
                atomicAdd(dst + 5, a1.y * inv);
                atomicAdd(dst + 6, a1.z * inv);
                atomicAdd(dst + 7, a1.w * inv);
            }
        }
    }
    __syncthreads();
    for (int i = threadIdx.x; i < NG * NH * C2; i += blockDim.x) {
        float v = sp[i];
        if (v != 0.f) red_f(&g_pooled[i], v);
    }
}

// ---------------- kernel 5: final projection --------------------------------
__global__ void k_final(const float* __restrict__ Wproj,
                        const float* __restrict__ bproj,
                        float* __restrict__ out) {
    int tid = threadIdx.x;
    if (tid >= NG * F_OUT) return;
    int g = tid / F_OUT;
    int o = tid % F_OUT;
    float acc = bproj[o];
#pragma unroll
    for (int t = 0; t < NH * C2; t++)
        acc = fmaf(g_pooled[g * (NH * C2) + t], Wproj[t * F_OUT + o], acc);
    out[g * F_OUT + o] = acc;
}

// ---------------- launch ----------------------------------------------------
extern "C" void kernel_launch(void* const* d_in, const int* in_sizes, int n_in,
                              void* d_out, int out_size) {
    const float* NF    = (const float*)d_in[0];
    const float* pos   = (const float*)d_in[1];
    const float* We    = (const float*)d_in[2];
    const float* be    = (const float*)d_in[3];
    const float* Wq    = (const float*)d_in[4];
    const float* Wk    = (const float*)d_in[5];
    const float* W1    = (const float*)d_in[6];
    const float* b1    = (const float*)d_in[7];
    const float* Wa    = (const float*)d_in[8];
    const float* Wv    = (const float*)d_in[9];
    const float* Wo    = (const float*)d_in[10];
    const float* Wproj = (const float*)d_in[11];
    const float* bproj = (const float*)d_in[12];
    const int*   ei    = (const int*)d_in[13];
    const int*   batch = (const int*)d_in[14];
    float* out = (float*)d_out;

    k_nodes<<<NODE_BLOCKS + 1, 256>>>(NF, We, be, Wq, Wk, W1, b1, Wa, Wv);
    k_edge_logit<<<(E_HALF + 255) / 256, 256>>>(pos, ei);
    k_edge_acc<<<(E_HALF + 255) / 256, 256>>>(ei, Wo);
    k_node_out<<<(N_NODES + 255) / 256, 256>>>(batch);
    k_final<<<1, 512>>>(Wproj, bproj, out);
}

// round 4
// speedup vs baseline: 2.3280x; 2.3280x over previous
#include <cuda_runtime.h>

#define N_NODES 10000
#define N_EDGES 160000
#define E_HALF  80000
#define C       16
#define C2      8
#define HID     64
#define NH      2
#define NG      16
#define F_IN    64
#define F_OUT   32
#define NI      65   // intervals = HID+1
#define CP      20   // padded row for shared S tables (bank spread)

#define NODE_BLOCKS 40   // ceil(10000/256)

// ---------------- scratch (device globals; no allocations allowed) ----------
__device__ __align__(16) float g_x[N_NODES * C];                 // [n][c]
__device__ __align__(16) float g_q[N_NODES * NH * C];            // [n][h][c]
__device__ __align__(16) float g_k[N_NODES * NH * C];            // [n][h][c]
__device__ float    g_dist[N_EDGES];
__device__ __align__(8) float g_logit[N_EDGES * NH];             // [e][h]
__device__ uchar2   g_idx[N_EDGES];                              // interval idx per head
__device__ __align__(8) unsigned g_m[N_NODES * NH];              // [n][h]
__device__ __align__(8) float    g_z[N_NODES * NH];              // [n][h]
__device__ __align__(16) float g_accp[N_NODES * NH * C2];        // projected acc [n][h][j]
__device__ float    g_pooled[NG * NH * C2];

// piecewise-linear tables:  wv0[c](df) = S0[c] + df*S1[c];  bias(df) = A0 + df*A1
__device__ float g_t [NH][HID];      // sorted breakpoints
__device__ __align__(16) float g_S0[NH][NI][C];
__device__ __align__(16) float g_S1[NH][NI][C];
__device__ float g_A0[NH][NI];
__device__ float g_A1[NH][NI];

// order-preserving float<->uint encoding for atomicMax on floats
__device__ __forceinline__ unsigned fenc(float f) {
    unsigned u = __float_as_uint(f);
    return (u & 0x80000000u) ? ~u : (u | 0x80000000u);
}
__device__ __forceinline__ float fdec(unsigned u) {
    return (u & 0x80000000u) ? __uint_as_float(u & 0x7fffffffu)
                             : __uint_as_float(~u);
}
#define ENC_NEG_INF 0x007FFFFFu   // fenc(-inf)

__device__ __forceinline__ void red_v4(float* p, float4 v) {
    asm volatile("red.global.add.v4.f32 [%0], {%1, %2, %3, %4};"
                 :: "l"(p), "f"(v.x), "f"(v.y), "f"(v.z), "f"(v.w) : "memory");
}
__device__ __forceinline__ void red_f(float* p, float v) {
    asm volatile("red.global.add.f32 [%0], %1;" :: "l"(p), "f"(v) : "memory");
}

// binary search over smem breakpoints: # strictly < df, result in [0,64]
__device__ __forceinline__ int bsearch64(const float* t, float df) {
    int lo = 0, hi = HID;
#pragma unroll
    for (int it = 0; it < 7; it++) {
        if (lo < hi) {
            int mid = (lo + hi) >> 1;
            if (t[mid] < df) lo = mid + 1; else hi = mid;
        }
    }
    return lo;
}

// ---------------- kernel 1: nodes (embed+q/k+init) + table block ------------
__global__ void __launch_bounds__(256)
k_nodes(const float* __restrict__ NF,
        const float* __restrict__ We,
        const float* __restrict__ be,
        const float* __restrict__ Wq,
        const float* __restrict__ Wk,
        const float* __restrict__ W1,
        const float* __restrict__ b1,
        const float* __restrict__ Wa,
        const float* __restrict__ Wv) {
    int tid = threadIdx.x;

    if (blockIdx.x == NODE_BLOCKS) {
        // ---- table-builder block ----
        __shared__ float raw[NH][HID];
        __shared__ float stt[NH][HID];
        if (tid < NH * HID) {
            int h = tid / HID, j = tid % HID;
            float w = W1[h * HID + j], b = b1[h * HID + j];
            raw[h][j] = (w != 0.f) ? (-b / w) : -1e30f;  // w==0: park at -inf
        }
        __syncthreads();
        if (tid < NH * HID) {
            int h = tid / HID, j = tid % HID;
            float v = raw[h][j];
            int rank = 0;
            for (int i = 0; i < HID; i++) {
                float o = raw[h][i];
                rank += (o < v || (o == v && i < j)) ? 1 : 0;
            }
            stt[h][rank] = v;
            g_t[h][rank] = v;
        }
        __syncthreads();
        if (tid < NH * NI) {
            int h = tid / NI, i = tid % NI;
            float lo = (i == 0)   ? stt[h][0] - 1.0f       : stt[h][i - 1];
            float hi = (i == HID) ? stt[h][HID - 1] + 1.0f : stt[h][i];
            float mid = 0.5f * (lo + hi);
            float S0[C], S1[C], A0 = 0.f, A1 = 0.f;
#pragma unroll
            for (int c = 0; c < C; c++) { S0[c] = 0.f; S1[c] = 0.f; }
            for (int j = 0; j < HID; j++) {
                float w = W1[h * HID + j], b = b1[h * HID + j];
                if (fmaf(w, mid, b) > 0.f) {
                    float wa = Wa[h * HID + j];
                    A0 = fmaf(b, wa, A0);
                    A1 = fmaf(w, wa, A1);
#pragma unroll
                    for (int c = 0; c < C; c++) {
                        float wv = Wv[(h * HID + j) * (C * 3) + 3 * c]; // m=0 slice
                        S0[c] = fmaf(b, wv, S0[c]);
                        S1[c] = fmaf(w, wv, S1[c]);
                    }
                }
            }
#pragma unroll
            for (int c = 0; c < C; c++) { g_S0[h][i][c] = S0[c]; g_S1[h][i][c] = S1[c]; }
            g_A0[h][i] = A0; g_A1[h][i] = A1;
        }
        if (tid < NG * NH * C2) g_pooled[tid] = 0.f;
        return;
    }

    // ---- node blocks ----
    __shared__ float sWe[F_IN * C];
    __shared__ float sbe[C];
    __shared__ float sWq[NH * C * C];
    __shared__ float sWk[NH * C * C];
    for (int i = tid; i < F_IN * C; i += blockDim.x) sWe[i] = We[i];
    for (int i = tid; i < C; i += blockDim.x) sbe[i] = be[i];
    for (int i = tid; i < NH * C * C; i += blockDim.x) { sWq[i] = Wq[i]; sWk[i] = Wk[i]; }
    __syncthreads();

    int n = blockIdx.x * blockDim.x + tid;
    if (n >= N_NODES) return;

    // init per-node scratch
    *(uint2*)(g_m + n * NH) = make_uint2(ENC_NEG_INF, ENC_NEG_INF);
    *(float2*)(g_z + n * NH) = make_float2(0.f, 0.f);
    float4 zf4 = make_float4(0.f, 0.f, 0.f, 0.f);
    float4* ac = (float4*)(g_accp + n * NH * C2);
#pragma unroll
    for (int i = 0; i < 4; i++) ac[i] = zf4;

    float x[C];
#pragma unroll
    for (int j = 0; j < C; j++) x[j] = sbe[j];
    const float4* nf4 = (const float4*)(NF + n * F_IN);
#pragma unroll
    for (int i4 = 0; i4 < F_IN / 4; i4++) {
        float4 v = nf4[i4];
        float vs[4] = { v.x, v.y, v.z, v.w };
#pragma unroll
        for (int k = 0; k < 4; k++) {
            float vv = vs[k];
            int i = i4 * 4 + k;
#pragma unroll
            for (int j = 0; j < C; j++) x[j] = fmaf(vv, sWe[i * C + j], x[j]);
        }
    }
#pragma unroll
    for (int j = 0; j < C; j++) g_x[n * C + j] = x[j];

#pragma unroll
    for (int h = 0; h < NH; h++) {
        float q[C], k[C];
#pragma unroll
        for (int j = 0; j < C; j++) { q[j] = 0.f; k[j] = 0.f; }
#pragma unroll
        for (int i = 0; i < C; i++) {
            float xi = x[i];
#pragma unroll
            for (int j = 0; j < C; j++) {
                q[j] = fmaf(xi, sWq[h * C * C + i * C + j], q[j]);
                k[j] = fmaf(xi, sWk[h * C * C + i * C + j], k[j]);
            }
        }
        float* qp = g_q + (n * NH + h) * C;
        float* kp = g_k + (n * NH + h) * C;
#pragma unroll
        for (int j = 0; j < C; j++) { qp[j] = q[j]; kp[j] = k[j]; }
    }
}

// ---------------- kernel 2: edge logits + segment max (2 edges/thread) ------
__global__ void __launch_bounds__(256)
k_edge_logit(const float* __restrict__ pos,
             const int* __restrict__ ei) {
    __shared__ float  st[NH][HID];
    __shared__ float2 sA[NH][NI];
    for (int i = threadIdx.x; i < NH * HID; i += blockDim.x)
        st[i / HID][i % HID] = g_t[i / HID][i % HID];
    for (int i = threadIdx.x; i < NH * NI; i += blockDim.x)
        sA[i / NI][i % NI] = make_float2(g_A0[i / NI][i % NI], g_A1[i / NI][i % NI]);
    __syncthreads();

    int i = blockIdx.x * blockDim.x + threadIdx.x;
    if (i >= E_HALF) return;

    int e[2]  = { i, i + E_HALF };
    int s[2], t[2];
#pragma unroll
    for (int u = 0; u < 2; u++) { s[u] = ei[e[u]]; t[u] = ei[N_EDGES + e[u]]; }

    float d[2], d2i[2];
#pragma unroll
    for (int u = 0; u < 2; u++) {
        float dx = pos[3 * t[u] + 0] - pos[3 * s[u] + 0];
        float dy = pos[3 * t[u] + 1] - pos[3 * s[u] + 1];
        float dz = pos[3 * t[u] + 2] - pos[3 * s[u] + 2];
        float d2 = dx * dx + dy * dy + dz * dz;
        d[u]   = sqrtf(d2);
        d2i[u] = 1.0f / d2;
    }

#pragma unroll
    for (int u = 0; u < 2; u++) {
        float df_h[NH] = { d[u], d2i[u] };
        float2 lg2;
        uchar2 ix2;
#pragma unroll
        for (int h = 0; h < NH; h++) {
            float df = df_h[h];
            int idx = bsearch64(st[h], df);
            float2 A = sA[h][idx];
            float ab = fmaf(df, A.y, A.x);

            const float4* qt = (const float4*)(g_q + (t[u] * NH + h) * C);
            const float4* ks = (const float4*)(g_k + (s[u] * NH + h) * C);
            float dot = 0.f;
#pragma unroll
            for (int i4 = 0; i4 < 4; i4++) {
                float4 a = qt[i4], b = ks[i4];
                dot += a.x * b.x + a.y * b.y + a.z * b.z + a.w * b.w;
            }
            float lg = fmaf(dot, 0.25f, ab);   // 1/sqrt(C) = 0.25
            (h == 0 ? lg2.x : lg2.y) = lg;
            (h == 0 ? ix2.x : ix2.y) = (unsigned char)idx;
            atomicMax(&g_m[t[u] * NH + h], fenc(lg));
        }
        g_dist[e[u]] = d[u];
        *(float2*)(g_logit + e[u] * NH) = lg2;
        g_idx[e[u]] = ix2;
    }
}

// ---------------- kernel 3: exp + projected message accumulate --------------
__global__ void __launch_bounds__(256)
k_edge_acc(const int* __restrict__ ei,
           const float* __restrict__ Wo) {
    __shared__ __align__(16) float sS0[NH * NI * CP];
    __shared__ __align__(16) float sS1[NH * NI * CP];
    __shared__ float sWo[NH * C * C2];   // li=0 slice: [h][c][j]
    for (int i = threadIdx.x; i < NH * NI * (C / 4); i += blockDim.x) {
        int hi4 = i / (C / 4);           // h*NI+interval
        int c4  = i % (C / 4);
        float4 a = ((const float4*)g_S0)[i];
        float4 b = ((const float4*)g_S1)[i];
        *(float4*)(sS0 + hi4 * CP + c4 * 4) = a;
        *(float4*)(sS1 + hi4 * CP + c4 * 4) = b;
    }
    for (int i = threadIdx.x; i < NH * C * C2; i += blockDim.x) {
        int h = i / (C * C2);
        int r = i % (C * C2);
        sWo[i] = Wo[h * 3 * C * C2 + r]; // li = 0 slice
    }
    __syncthreads();

    int i = blockIdx.x * blockDim.x + threadIdx.x;
    if (i >= E_HALF) return;
    int e[2] = { i, i + E_HALF };

#pragma unroll
    for (int u = 0; u < 2; u++) {
        int s = ei[e[u]];
        int t = ei[N_EDGES + e[u]];

        float4 xs[4];
        {
            const float4* xp = (const float4*)(g_x + s * C);
#pragma unroll
            for (int i4 = 0; i4 < 4; i4++) xs[i4] = xp[i4];
        }
        float dd = g_dist[e[u]];
        float df_h[NH] = { dd, 1.0f / (dd * dd) };

        float2 lg2 = *(const float2*)(g_logit + e[u] * NH);
        uchar2 ix2 = g_idx[e[u]];
        uint2  m2  = *(const uint2*)(g_m + t * NH);
        float lg_h[NH] = { lg2.x, lg2.y };
        float m_h [NH] = { fdec(m2.x), fdec(m2.y) };
        int   ix_h[NH] = { ix2.x, ix2.y };

#pragma unroll
        for (int h = 0; h < NH; h++) {
            float ex = __expf(lg_h[h] - m_h[h]);
            red_f(&g_z[t * NH + h], ex);

            float df = df_h[h];
            const float* p0 = sS0 + (h * NI + ix_h[h]) * CP;
            const float* p1 = sS1 + (h * NI + ix_h[h]) * CP;
            float p[C2];
#pragma unroll
            for (int j = 0; j < C2; j++) p[j] = 0.f;
#pragma unroll
            for (int i4 = 0; i4 < 4; i4++) {
                float4 a = *(const float4*)(p0 + i4 * 4);
                float4 b = *(const float4*)(p1 + i4 * 4);
                float4 xv = xs[i4];
                float w0 = fmaf(df, b.x, a.x) * xv.x;
                float w1 = fmaf(df, b.y, a.y) * xv.y;
                float w2 = fmaf(df, b.z, a.z) * xv.z;
                float w3 = fmaf(df, b.w, a.w) * xv.w;
                const float* wo = sWo + h * C * C2 + (i4 * 4) * C2;
#pragma unroll
                for (int j = 0; j < C2; j++) {
                    p[j] = fmaf(w0, wo[0 * C2 + j], p[j]);
                    p[j] = fmaf(w1, wo[1 * C2 + j], p[j]);
                    p[j] = fmaf(w2, wo[2 * C2 + j], p[j]);
                    p[j] = fmaf(w3, wo[3 * C2 + j], p[j]);
                }
            }
            float* accp = g_accp + (t * NH + h) * C2;
            red_v4(accp,     make_float4(ex * p[0], ex * p[1], ex * p[2], ex * p[3]));
            red_v4(accp + 4, make_float4(ex * p[4], ex * p[5], ex * p[6], ex * p[7]));
        }
    }
}

// ---------------- kernel 4: normalize + warp-aggregated batch pool ----------
__global__ void __launch_bounds__(256)
k_node_out(const int* __restrict__ batch) {
    __shared__ float sp[NG * NH * C2];
    for (int i = threadIdx.x; i < NG * NH * C2; i += blockDim.x) sp[i] = 0.f;
    __syncthreads();

    int n = blockIdx.x * blockDim.x + threadIdx.x;
    int lane = threadIdx.x & 31;

    float v[NH * C2];
#pragma unroll
    for (int i = 0; i < NH * C2; i++) v[i] = 0.f;
    int g = 0;
    bool valid = (n < N_NODES);
    if (valid) {
        g = batch[n];
        float2 z2 = *(const float2*)(g_z + n * NH);
        float z_h[NH] = { z2.x, z2.y };
#pragma unroll
        for (int h = 0; h < NH; h++) {
            float z = z_h[h];
            if (z > 0.f) {
                float inv = 1.0f / z;
                const float4* ap = (const float4*)(g_accp + (n * NH + h) * C2);
                float4 a0 = ap[0], a1 = ap[1];
                v[h * C2 + 0] = a0.x * inv; v[h * C2 + 1] = a0.y * inv;
                v[h * C2 + 2] = a0.z * inv; v[h * C2 + 3] = a0.w * inv;
                v[h * C2 + 4] = a1.x * inv; v[h * C2 + 5] = a1.y * inv;
                v[h * C2 + 6] = a1.z * inv; v[h * C2 + 7] = a1.w * inv;
            }
        }
    }

    int g0 = __shfl_sync(0xffffffffu, g, 0);
    bool uniform = __all_sync(0xffffffffu, valid && (g == g0));
    if (uniform) {
        // butterfly reduce all 16 values across the warp, lane 0 commits
#pragma unroll
        for (int i = 0; i < NH * C2; i++) {
#pragma unroll
            for (int ofs = 16; ofs > 0; ofs >>= 1)
                v[i] += __shfl_xor_sync(0xffffffffu, v[i], ofs);
        }
        if (lane == 0) {
            float* dst = sp + g0 * NH * C2;
#pragma unroll
            for (int i = 0; i < NH * C2; i++) atomicAdd(dst + i, v[i]);
        }
    } else if (valid) {
        float* dst = sp + g * NH * C2;
#pragma unroll
        for (int i = 0; i < NH * C2; i++) atomicAdd(dst + i, v[i]);
    }
    __syncthreads();
    for (int i = threadIdx.x; i < NG * NH * C2; i += blockDim.x) {
        float w = sp[i];
        if (w != 0.f) red_f(&g_pooled[i], w);
    }
}

// ---------------- kernel 5: final projection --------------------------------
__global__ void k_final(const float* __restrict__ Wproj,
                        const float* __restrict__ bproj,
                        float* __restrict__ out) {
    int tid = threadIdx.x;
    if (tid >= NG * F_OUT) return;
    int g = tid / F_OUT;
    int o = tid % F_OUT;
    float acc = bproj[o];
#pragma unroll
    for (int t = 0; t < NH * C2; t++)
        acc = fmaf(g_pooled[g * (NH * C2) + t], Wproj[t * F_OUT + o], acc);
    out[g * F_OUT + o] = acc;
}

// ---------------- launch ----------------------------------------------------
extern "C" void kernel_launch(void* const* d_in, const int* in_sizes, int n_in,
                              void* d_out, int out_size) {
    const float* NF    = (const float*)d_in[0];
    const float* pos   = (const float*)d_in[1];
    const float* We    = (const float*)d_in[2];
    const float* be    = (const float*)d_in[3];
    const float* Wq    = (const float*)d_in[4];
    const float* Wk    = (const float*)d_in[5];
    const float* W1    = (const float*)d_in[6];
    const float* b1    = (const float*)d_in[7];
    const float* Wa    = (const float*)d_in[8];
    const float* Wv    = (const float*)d_in[9];
    const float* Wo    = (const float*)d_in[10];
    const float* Wproj = (const float*)d_in[11];
    const float* bproj = (const float*)d_in[12];
    const int*   ei    = (const int*)d_in[13];
    const int*   batch = (const int*)d_in[14];
    float* out = (float*)d_out;

    k_nodes<<<NODE_BLOCKS + 1, 256>>>(NF, We, be, Wq, Wk, W1, b1, Wa, Wv);
    k_edge_logit<<<(E_HALF + 255) / 256, 256>>>(pos, ei);
    k_edge_acc<<<(E_HALF + 255) / 256, 256>>>(ei, Wo);
    k_node_out<<<(N_NODES + 255) / 256, 256>>>(batch);
    k_final<<<1, 512>>>(Wproj, bproj, out);
}

// round 5
// speedup vs baseline: 3.0222x; 1.2982x over previous
#include <cuda_runtime.h>

#define N_NODES 10000
#define N_EDGES 160000
#define E_HALF  80000
#define C       16
#define C2      8
#define HID     64
#define NH      2
#define NG      16
#define F_IN    64
#define F_OUT   32
#define NI      65   // intervals = HID+1
#define CP      20   // padded row for shared S tables (bank spread)

#define NODE_BLOCKS 40   // ceil(10000/256)
#define NO_THREADS  (N_NODES * NH)           // 20000
#define NO_BLOCKS   ((NO_THREADS + 255) / 256)  // 79

// ---------------- scratch (device globals; no allocations allowed) ----------
__device__ __align__(16) float g_x[N_NODES * C];                 // [n][c]
__device__ __align__(16) float g_q[N_NODES * NH * C];            // [n][h][c]
__device__ __align__(16) float g_k[N_NODES * NH * C];            // [n][h][c]
__device__ __align__(16) float4 g_edat[N_EDGES];                 // {dist, lg0, lg1, idx bits}
__device__ unsigned g_st[N_EDGES];                               // s | t<<16
__device__ __align__(8) unsigned g_m[N_NODES * NH];              // [n][h]
__device__ __align__(8) float    g_z[N_NODES * NH];              // [n][h]
__device__ __align__(16) float g_accp[N_NODES * NH * C2];        // projected acc [n][h][j]
__device__ float    g_pooled[NG * NH * C2];
__device__ int      g_cnt;

// piecewise-linear tables:  wv0[c](df) = S0[c] + df*S1[c];  bias(df) = A0 + df*A1
__device__ float g_t [NH][HID];      // sorted breakpoints
__device__ __align__(16) float g_S0[NH][NI][C];
__device__ __align__(16) float g_S1[NH][NI][C];
__device__ float g_A0[NH][NI];
__device__ float g_A1[NH][NI];

// order-preserving float<->uint encoding for atomicMax on floats
__device__ __forceinline__ unsigned fenc(float f) {
    unsigned u = __float_as_uint(f);
    return (u & 0x80000000u) ? ~u : (u | 0x80000000u);
}
__device__ __forceinline__ float fdec(unsigned u) {
    return (u & 0x80000000u) ? __uint_as_float(u & 0x7fffffffu)
                             : __uint_as_float(~u);
}
#define ENC_NEG_INF 0x007FFFFFu   // fenc(-inf)

__device__ __forceinline__ void red_v4(float* p, float4 v) {
    asm volatile("red.global.add.v4.f32 [%0], {%1, %2, %3, %4};"
                 :: "l"(p), "f"(v.x), "f"(v.y), "f"(v.z), "f"(v.w) : "memory");
}
__device__ __forceinline__ void red_f(float* p, float v) {
    asm volatile("red.global.add.f32 [%0], %1;" :: "l"(p), "f"(v) : "memory");
}

// binary search over smem breakpoints: # strictly < df, result in [0,64]
__device__ __forceinline__ int bsearch64(const float* t, float df) {
    int lo = 0, hi = HID;
#pragma unroll
    for (int it = 0; it < 7; it++) {
        if (lo < hi) {
            int mid = (lo + hi) >> 1;
            if (t[mid] < df) lo = mid + 1; else hi = mid;
        }
    }
    return lo;
}

// ---------------- kernel 1: nodes (embed+q/k+init) + table block ------------
__global__ void __launch_bounds__(256)
k_nodes(const float* __restrict__ NF,
        const float* __restrict__ We,
        const float* __restrict__ be,
        const float* __restrict__ Wq,
        const float* __restrict__ Wk,
        const float* __restrict__ W1,
        const float* __restrict__ b1,
        const float* __restrict__ Wa,
        const float* __restrict__ Wv) {
    int tid = threadIdx.x;

    if (blockIdx.x == NODE_BLOCKS) {
        // ---- table-builder block ----
        __shared__ float raw[NH][HID];
        __shared__ float stt[NH][HID];
        if (tid == 0) g_cnt = 0;
        if (tid < NH * HID) {
            int h = tid / HID, j = tid % HID;
            float w = W1[h * HID + j], b = b1[h * HID + j];
            raw[h][j] = (w != 0.f) ? (-b / w) : -1e30f;  // w==0: park at -inf
        }
        __syncthreads();
        if (tid < NH * HID) {
            int h = tid / HID, j = tid % HID;
            float v = raw[h][j];
            int rank = 0;
            for (int i = 0; i < HID; i++) {
                float o = raw[h][i];
                rank += (o < v || (o == v && i < j)) ? 1 : 0;
            }
            stt[h][rank] = v;
            g_t[h][rank] = v;
        }
        __syncthreads();
        if (tid < NH * NI) {
            int h = tid / NI, i = tid % NI;
            float lo = (i == 0)   ? stt[h][0] - 1.0f       : stt[h][i - 1];
            float hi = (i == HID) ? stt[h][HID - 1] + 1.0f : stt[h][i];
            float mid = 0.5f * (lo + hi);
            float S0[C], S1[C], A0 = 0.f, A1 = 0.f;
#pragma unroll
            for (int c = 0; c < C; c++) { S0[c] = 0.f; S1[c] = 0.f; }
            for (int j = 0; j < HID; j++) {
                float w = W1[h * HID + j], b = b1[h * HID + j];
                if (fmaf(w, mid, b) > 0.f) {
                    float wa = Wa[h * HID + j];
                    A0 = fmaf(b, wa, A0);
                    A1 = fmaf(w, wa, A1);
#pragma unroll
                    for (int c = 0; c < C; c++) {
                        float wv = Wv[(h * HID + j) * (C * 3) + 3 * c]; // m=0 slice
                        S0[c] = fmaf(b, wv, S0[c]);
                        S1[c] = fmaf(w, wv, S1[c]);
                    }
                }
            }
#pragma unroll
            for (int c = 0; c < C; c++) { g_S0[h][i][c] = S0[c]; g_S1[h][i][c] = S1[c]; }
            g_A0[h][i] = A0; g_A1[h][i] = A1;
        }
        if (tid < NG * NH * C2) g_pooled[tid] = 0.f;
        return;
    }

    // ---- node blocks ----
    __shared__ float sWe[F_IN * C];
    __shared__ float sbe[C];
    __shared__ float sWq[NH * C * C];
    __shared__ float sWk[NH * C * C];
    for (int i = tid; i < F_IN * C; i += blockDim.x) sWe[i] = We[i];
    for (int i = tid; i < C; i += blockDim.x) sbe[i] = be[i];
    for (int i = tid; i < NH * C * C; i += blockDim.x) { sWq[i] = Wq[i]; sWk[i] = Wk[i]; }
    __syncthreads();

    int n = blockIdx.x * blockDim.x + tid;
    if (n >= N_NODES) return;

    // init per-node scratch
    *(uint2*)(g_m + n * NH) = make_uint2(ENC_NEG_INF, ENC_NEG_INF);
    *(float2*)(g_z + n * NH) = make_float2(0.f, 0.f);
    float4 zf4 = make_float4(0.f, 0.f, 0.f, 0.f);
    float4* ac = (float4*)(g_accp + n * NH * C2);
#pragma unroll
    for (int i = 0; i < 4; i++) ac[i] = zf4;

    float x[C];
#pragma unroll
    for (int j = 0; j < C; j++) x[j] = sbe[j];
    const float4* nf4 = (const float4*)(NF + n * F_IN);
#pragma unroll
    for (int i4 = 0; i4 < F_IN / 4; i4++) {
        float4 v = nf4[i4];
        float vs[4] = { v.x, v.y, v.z, v.w };
#pragma unroll
        for (int k = 0; k < 4; k++) {
            float vv = vs[k];
            int i = i4 * 4 + k;
#pragma unroll
            for (int j = 0; j < C; j++) x[j] = fmaf(vv, sWe[i * C + j], x[j]);
        }
    }
#pragma unroll
    for (int j = 0; j < C; j++) g_x[n * C + j] = x[j];

#pragma unroll
    for (int h = 0; h < NH; h++) {
        float q[C], k[C];
#pragma unroll
        for (int j = 0; j < C; j++) { q[j] = 0.f; k[j] = 0.f; }
#pragma unroll
        for (int i = 0; i < C; i++) {
            float xi = x[i];
#pragma unroll
            for (int j = 0; j < C; j++) {
                q[j] = fmaf(xi, sWq[h * C * C + i * C + j], q[j]);
                k[j] = fmaf(xi, sWk[h * C * C + i * C + j], k[j]);
            }
        }
        float* qp = g_q + (n * NH + h) * C;
        float* kp = g_k + (n * NH + h) * C;
#pragma unroll
        for (int j = 0; j < C; j++) { qp[j] = q[j]; kp[j] = k[j]; }
    }
}

// ---------------- kernel 2: edge logits + segment max (2 edges/thread) ------
__global__ void __launch_bounds__(256)
k_edge_logit(const float* __restrict__ pos,
             const int* __restrict__ ei) {
    __shared__ float  st[NH][HID];
    __shared__ float2 sA[NH][NI];
    for (int i = threadIdx.x; i < NH * HID; i += blockDim.x)
        st[i / HID][i % HID] = g_t[i / HID][i % HID];
    for (int i = threadIdx.x; i < NH * NI; i += blockDim.x)
        sA[i / NI][i % NI] = make_float2(g_A0[i / NI][i % NI], g_A1[i / NI][i % NI]);
    __syncthreads();

    int i = blockIdx.x * blockDim.x + threadIdx.x;
    if (i >= E_HALF) return;

    int e[2]  = { i, i + E_HALF };
    int s[2], t[2];
#pragma unroll
    for (int u = 0; u < 2; u++) { s[u] = ei[e[u]]; t[u] = ei[N_EDGES + e[u]]; }

    float d[2], d2i[2];
#pragma unroll
    for (int u = 0; u < 2; u++) {
        float dx = pos[3 * t[u] + 0] - pos[3 * s[u] + 0];
        float dy = pos[3 * t[u] + 1] - pos[3 * s[u] + 1];
        float dz = pos[3 * t[u] + 2] - pos[3 * s[u] + 2];
        float d2 = dx * dx + dy * dy + dz * dz;
        d[u]   = sqrtf(d2);
        d2i[u] = 1.0f / d2;
    }

#pragma unroll
    for (int u = 0; u < 2; u++) {
        float df_h[NH] = { d[u], d2i[u] };
        float lg_h[NH];
        int   ix_h[NH];
#pragma unroll
        for (int h = 0; h < NH; h++) {
            float df = df_h[h];
            int idx = bsearch64(st[h], df);
            float2 A = sA[h][idx];
            float ab = fmaf(df, A.y, A.x);

            const float4* qt = (const float4*)(g_q + (t[u] * NH + h) * C);
            const float4* ks = (const float4*)(g_k + (s[u] * NH + h) * C);
            float dot = 0.f;
#pragma unroll
            for (int i4 = 0; i4 < 4; i4++) {
                float4 a = qt[i4], b = ks[i4];
                dot += a.x * b.x + a.y * b.y + a.z * b.z + a.w * b.w;
            }
            float lg = fmaf(dot, 0.25f, ab);   // 1/sqrt(C) = 0.25
            lg_h[h] = lg;
            ix_h[h] = idx;
            atomicMax(&g_m[t[u] * NH + h], fenc(lg));
        }
        unsigned ixpack = (unsigned)ix_h[0] | ((unsigned)ix_h[1] << 8);
        g_edat[e[u]] = make_float4(d[u], lg_h[0], lg_h[1], __uint_as_float(ixpack));
        g_st[e[u]]   = (unsigned)s[u] | ((unsigned)t[u] << 16);
    }
}

// ---------------- kernel 3: exp + projected message accumulate --------------
__global__ void __launch_bounds__(256)
k_edge_acc(const float* __restrict__ Wo) {
    __shared__ __align__(16) float sS0[NH * NI * CP];
    __shared__ __align__(16) float sS1[NH * NI * CP];
    __shared__ float sWo[NH * C * C2];   // li=0 slice: [h][c][j]
    for (int i = threadIdx.x; i < NH * NI * (C / 4); i += blockDim.x) {
        int hi4 = i / (C / 4);           // h*NI+interval
        int c4  = i % (C / 4);
        float4 a = ((const float4*)g_S0)[i];
        float4 b = ((const float4*)g_S1)[i];
        *(float4*)(sS0 + hi4 * CP + c4 * 4) = a;
        *(float4*)(sS1 + hi4 * CP + c4 * 4) = b;
    }
    for (int i = threadIdx.x; i < NH * C * C2; i += blockDim.x) {
        int h = i / (C * C2);
        int r = i % (C * C2);
        sWo[i] = Wo[h * 3 * C * C2 + r]; // li = 0 slice
    }
    __syncthreads();

    int i = blockIdx.x * blockDim.x + threadIdx.x;
    if (i >= E_HALF) return;
    int e[2] = { i, i + E_HALF };

#pragma unroll
    for (int u = 0; u < 2; u++) {
        unsigned stp = g_st[e[u]];
        int s = (int)(stp & 0xffffu);
        int t = (int)(stp >> 16);

        float4 ed = g_edat[e[u]];
        float dd = ed.x;
        unsigned ixpack = __float_as_uint(ed.w);

        float4 xs[4];
        {
            const float4* xp = (const float4*)(g_x + s * C);
#pragma unroll
            for (int i4 = 0; i4 < 4; i4++) xs[i4] = xp[i4];
        }
        float df_h[NH] = { dd, 1.0f / (dd * dd) };

        uint2  m2  = *(const uint2*)(g_m + t * NH);
        float lg_h[NH] = { ed.y, ed.z };
        float m_h [NH] = { fdec(m2.x), fdec(m2.y) };
        int   ix_h[NH] = { (int)(ixpack & 0xffu), (int)(ixpack >> 8) };

#pragma unroll
        for (int h = 0; h < NH; h++) {
            float ex = __expf(lg_h[h] - m_h[h]);
            red_f(&g_z[t * NH + h], ex);

            float df = df_h[h];
            const float* p0 = sS0 + (h * NI + ix_h[h]) * CP;
            const float* p1 = sS1 + (h * NI + ix_h[h]) * CP;
            float p[C2];
#pragma unroll
            for (int j = 0; j < C2; j++) p[j] = 0.f;
#pragma unroll
            for (int i4 = 0; i4 < 4; i4++) {
                float4 a = *(const float4*)(p0 + i4 * 4);
                float4 b = *(const float4*)(p1 + i4 * 4);
                float4 xv = xs[i4];
                float w0 = fmaf(df, b.x, a.x) * xv.x;
                float w1 = fmaf(df, b.y, a.y) * xv.y;
                float w2 = fmaf(df, b.z, a.z) * xv.z;
                float w3 = fmaf(df, b.w, a.w) * xv.w;
                const float* wo = sWo + h * C * C2 + (i4 * 4) * C2;
#pragma unroll
                for (int j = 0; j < C2; j++) {
                    p[j] = fmaf(w0, wo[0 * C2 + j], p[j]);
                    p[j] = fmaf(w1, wo[1 * C2 + j], p[j]);
                    p[j] = fmaf(w2, wo[2 * C2 + j], p[j]);
                    p[j] = fmaf(w3, wo[3 * C2 + j], p[j]);
                }
            }
            float* accp = g_accp + (t * NH + h) * C2;
            red_v4(accp,     make_float4(ex * p[0], ex * p[1], ex * p[2], ex * p[3]));
            red_v4(accp + 4, make_float4(ex * p[4], ex * p[5], ex * p[6], ex * p[7]));
        }
    }
}

// ---------------- kernel 4: normalize + pool + fused final projection -------
__global__ void __launch_bounds__(256)
k_node_out(const int* __restrict__ batch,
           const float* __restrict__ Wproj,
           const float* __restrict__ bproj,
           float* __restrict__ out) {
    int tid  = threadIdx.x;
    int gi   = blockIdx.x * blockDim.x + tid;      // (n,h) pair index
    int lane = tid & 31;

    int n = gi >> 1;
    int h = gi & 1;
    bool valid = (gi < NO_THREADS);

    float v[C2];
#pragma unroll
    for (int j = 0; j < C2; j++) v[j] = 0.f;
    int g = 0;
    if (valid) {
        g = batch[n];
        float z = g_z[n * NH + h];
        if (z > 0.f) {
            float inv = 1.0f / z;
            const float4* ap = (const float4*)(g_accp + (n * NH + h) * C2);
            float4 a0 = ap[0], a1 = ap[1];
            v[0] = a0.x * inv; v[1] = a0.y * inv; v[2] = a0.z * inv; v[3] = a0.w * inv;
            v[4] = a1.x * inv; v[5] = a1.y * inv; v[6] = a1.z * inv; v[7] = a1.w * inv;
        }
    }

    int g0 = __shfl_sync(0xffffffffu, g, 0);
    bool uniform = __all_sync(0xffffffffu, valid && (g == g0));
    if (uniform) {
        // parity-preserving butterfly: each lane ends with its h-class total
#pragma unroll
        for (int j = 0; j < C2; j++) {
#pragma unroll
            for (int ofs = 16; ofs >= 2; ofs >>= 1)
                v[j] += __shfl_xor_sync(0xffffffffu, v[j], ofs);
        }
        if (lane < 2) {   // lane0: h=0 sums; lane1: h=1 sums
            float* dst = g_pooled + (g0 * NH + h) * C2;
            red_v4(dst,     make_float4(v[0], v[1], v[2], v[3]));
            red_v4(dst + 4, make_float4(v[4], v[5], v[6], v[7]));
        }
    } else if (valid) {
        // rotated per-lane REDs (bounded conflicts)
        float* dst = g_pooled + (g * NH + h) * C2;
#pragma unroll
        for (int jj = 0; jj < C2; jj++) {
            int j = (jj + lane) & (C2 - 1);
            red_f(dst + j, v[j]);
        }
    }

    // ---- last-block-done: fused final projection ----
    __shared__ int s_last;
    __threadfence();
    if (tid == 0) {
        int done = atomicAdd(&g_cnt, 1);
        s_last = (done == NO_BLOCKS - 1);
    }
    __syncthreads();
    if (s_last) {
        __threadfence();
#pragma unroll
        for (int r = 0; r < 2; r++) {
            int idx = tid + r * 256;          // 512 outputs
            int gg = idx / F_OUT;
            int oo = idx % F_OUT;
            float acc = bproj[oo];
#pragma unroll
            for (int t2 = 0; t2 < NH * C2; t2++)
                acc = fmaf(g_pooled[gg * (NH * C2) + t2], Wproj[t2 * F_OUT + oo], acc);
            out[gg * F_OUT + oo] = acc;
        }
    }
}

// ---------------- launch ----------------------------------------------------
extern "C" void kernel_launch(void* const* d_in, const int* in_sizes, int n_in,
                              void* d_out, int out_size) {
    const float* NF    = (const float*)d_in[0];
    const float* pos   = (const float*)d_in[1];
    const float* We    = (const float*)d_in[2];
    const float* be    = (const float*)d_in[3];
    const float* Wq    = (const float*)d_in[4];
    const float* Wk    = (const float*)d_in[5];
    const float* W1    = (const float*)d_in[6];
    const float* b1    = (const float*)d_in[7];
    const float* Wa    = (const float*)d_in[8];
    const float* Wv    = (const float*)d_in[9];
    const float* Wo    = (const float*)d_in[10];
    const float* Wproj = (const float*)d_in[11];
    const float* bproj = (const float*)d_in[12];
    const int*   ei    = (const int*)d_in[13];
    const int*   batch = (const int*)d_in[14];
    float* out = (float*)d_out;

    k_nodes<<<NODE_BLOCKS + 1, 256>>>(NF, We, be, Wq, Wk, W1, b1, Wa, Wv);
    k_edge_logit<<<(E_HALF + 255) / 256, 256>>>(pos, ei);
    k_edge_acc<<<(E_HALF + 255) / 256, 256>>>(Wo);
    k_node_out<<<NO_BLOCKS, 256>>>(batch, Wproj, bproj, out);
}

// round 6
// speedup vs baseline: 3.1273x; 1.0348x over previous
#include <cuda_runtime.h>

#define N_NODES 10000
#define N_EDGES 160000
#define E_HALF  80000
#define C       16
#define C2      8
#define HID     64
#define NH      2
#define NG      16
#define F_IN    64
#define F_OUT   32
#define NI      65   // intervals = HID+1

#define NODE_BLOCKS 40                    // ceil(10000/256)
#define EL_BLOCKS   313                   // ceil(80000/256)
#define U_BLOCKS    40                    // node u-vector blocks
#define NO_THREADS  (N_NODES * NH)        // 20000
#define NO_BLOCKS   ((NO_THREADS + 255) / 256)  // 79

// ---------------- scratch (device globals; no allocations allowed) ----------
__device__ __align__(16) float g_x[N_NODES * C];                 // [n][c]
__device__ __align__(16) float g_q[N_NODES * NH * C];            // [n][h][c]
__device__ __align__(16) float g_k[N_NODES * NH * C];            // [n][h][c]
__device__ __align__(16) float g_u[N_NODES * NH * 16];           // [n][h][u0(8),u1(8)]
__device__ __align__(16) float4 g_edat[N_EDGES];                 // {dist, lg0, lg1, idx bits}
__device__ unsigned g_st[N_EDGES];                               // s | t<<16
__device__ __align__(8) unsigned g_m[N_NODES * NH];              // [n][h]
__device__ __align__(8) float    g_z[N_NODES * NH];              // [n][h]
__device__ __align__(16) float g_accp[N_NODES * NH * C2];        // projected acc [n][h][j]
__device__ float    g_pooled[NG * NH * C2];
__device__ int      g_cnt;
__device__ int      g_fast;

// piecewise-linear tables:  wv0[c](df) = S0[c] + df*S1[c];  bias(df) = A0 + df*A1
__device__ float g_t [NH][HID];      // sorted breakpoints
__device__ __align__(16) float g_S0[NH][NI][C];
__device__ __align__(16) float g_S1[NH][NI][C];
__device__ float g_A0[NH][NI];
__device__ float g_A1[NH][NI];

// order-preserving float<->uint encoding for atomicMax on floats
__device__ __forceinline__ unsigned fenc(float f) {
    unsigned u = __float_as_uint(f);
    return (u & 0x80000000u) ? ~u : (u | 0x80000000u);
}
__device__ __forceinline__ float fdec(unsigned u) {
    return (u & 0x80000000u) ? __uint_as_float(u & 0x7fffffffu)
                             : __uint_as_float(~u);
}
#define ENC_NEG_INF 0x007FFFFFu   // fenc(-inf)

__device__ __forceinline__ void red_v4(float* p, float4 v) {
    asm volatile("red.global.add.v4.f32 [%0], {%1, %2, %3, %4};"
                 :: "l"(p), "f"(v.x), "f"(v.y), "f"(v.z), "f"(v.w) : "memory");
}
__device__ __forceinline__ void red_f(float* p, float v) {
    asm volatile("red.global.add.f32 [%0], %1;" :: "l"(p), "f"(v) : "memory");
}

// binary search (global-memory breakpoints; slow fallback path only)
__device__ __forceinline__ int bsearch64g(const float* t, float df) {
    int lo = 0, hi = HID;
#pragma unroll
    for (int it = 0; it < 7; it++) {
        if (lo < hi) {
            int mid = (lo + hi) >> 1;
            if (__ldg(t + mid) < df) lo = mid + 1; else hi = mid;
        }
    }
    return lo;
}

// ---------------- kernel 1: nodes (embed+q/k+init) + table block ------------
__global__ void __launch_bounds__(256)
k_nodes(const float* __restrict__ NF,
        const float* __restrict__ We,
        const float* __restrict__ be,
        const float* __restrict__ Wq,
        const float* __restrict__ Wk,
        const float* __restrict__ W1,
        const float* __restrict__ b1,
        const float* __restrict__ Wa,
        const float* __restrict__ Wv) {
    int tid = threadIdx.x;

    if (blockIdx.x == NODE_BLOCKS) {
        // ---- table-builder block ----
        __shared__ float raw[NH][HID];
        __shared__ float stt[NH][HID];
        if (tid == 0) g_cnt = 0;
        if (tid < NH * HID) {
            int h = tid / HID, j = tid % HID;
            float w = W1[h * HID + j], b = b1[h * HID + j];
            raw[h][j] = (w != 0.f) ? (-b / w) : -1e30f;  // w==0: park at -inf
        }
        __syncthreads();
        if (tid < NH * HID) {
            int h = tid / HID, j = tid % HID;
            float v = raw[h][j];
            int rank = 0;
            for (int i = 0; i < HID; i++) {
                float o = raw[h][i];
                rank += (o < v || (o == v && i < j)) ? 1 : 0;
            }
            stt[h][rank] = v;
            g_t[h][rank] = v;
        }
        __syncthreads();
        if (tid == 0) {
            int npos = 0;
            for (int h = 0; h < NH; h++)
                for (int j = 0; j < HID; j++) npos += (stt[h][j] > 0.f) ? 1 : 0;
            g_fast = (npos == 0) ? 1 : 0;
        }
        if (tid < NH * NI) {
            int h = tid / NI, i = tid % NI;
            float lo = (i == 0)   ? stt[h][0] - 1.0f       : stt[h][i - 1];
            float hi = (i == HID) ? stt[h][HID - 1] + 1.0f : stt[h][i];
            float mid = 0.5f * (lo + hi);
            float S0[C], S1[C], A0 = 0.f, A1 = 0.f;
#pragma unroll
            for (int c = 0; c < C; c++) { S0[c] = 0.f; S1[c] = 0.f; }
            for (int j = 0; j < HID; j++) {
                float w = W1[h * HID + j], b = b1[h * HID + j];
                if (fmaf(w, mid, b) > 0.f) {
                    float wa = Wa[h * HID + j];
                    A0 = fmaf(b, wa, A0);
                    A1 = fmaf(w, wa, A1);
#pragma unroll
                    for (int c = 0; c < C; c++) {
                        float wv = Wv[(h * HID + j) * (C * 3) + 3 * c]; // m=0 slice
                        S0[c] = fmaf(b, wv, S0[c]);
                        S1[c] = fmaf(w, wv, S1[c]);
                    }
                }
            }
#pragma unroll
            for (int c = 0; c < C; c++) { g_S0[h][i][c] = S0[c]; g_S1[h][i][c] = S1[c]; }
            g_A0[h][i] = A0; g_A1[h][i] = A1;
        }
        if (tid < NG * NH * C2) g_pooled[tid] = 0.f;
        return;
    }

    // ---- node blocks ----
    __shared__ float sWe[F_IN * C];
    __shared__ float sbe[C];
    __shared__ float sWq[NH * C * C];
    __shared__ float sWk[NH * C * C];
    for (int i = tid; i < F_IN * C; i += blockDim.x) sWe[i] = We[i];
    for (int i = tid; i < C; i += blockDim.x) sbe[i] = be[i];
    for (int i = tid; i < NH * C * C; i += blockDim.x) { sWq[i] = Wq[i]; sWk[i] = Wk[i]; }
    __syncthreads();

    int n = blockIdx.x * blockDim.x + tid;
    if (n >= N_NODES) return;

    // init per-node scratch
    *(uint2*)(g_m + n * NH) = make_uint2(ENC_NEG_INF, ENC_NEG_INF);
    *(float2*)(g_z + n * NH) = make_float2(0.f, 0.f);
    float4 zf4 = make_float4(0.f, 0.f, 0.f, 0.f);
    float4* ac = (float4*)(g_accp + n * NH * C2);
#pragma unroll
    for (int i = 0; i < 4; i++) ac[i] = zf4;

    float x[C];
#pragma unroll
    for (int j = 0; j < C; j++) x[j] = sbe[j];
    const float4* nf4 = (const float4*)(NF + n * F_IN);
#pragma unroll
    for (int i4 = 0; i4 < F_IN / 4; i4++) {
        float4 v = nf4[i4];
        float vs[4] = { v.x, v.y, v.z, v.w };
#pragma unroll
        for (int k = 0; k < 4; k++) {
            float vv = vs[k];
            int i = i4 * 4 + k;
#pragma unroll
            for (int j = 0; j < C; j++) x[j] = fmaf(vv, sWe[i * C + j], x[j]);
        }
    }
#pragma unroll
    for (int j = 0; j < C; j++) g_x[n * C + j] = x[j];

#pragma unroll
    for (int h = 0; h < NH; h++) {
        float q[C], k[C];
#pragma unroll
        for (int j = 0; j < C; j++) { q[j] = 0.f; k[j] = 0.f; }
#pragma unroll
        for (int i = 0; i < C; i++) {
            float xi = x[i];
#pragma unroll
            for (int j = 0; j < C; j++) {
                q[j] = fmaf(xi, sWq[h * C * C + i * C + j], q[j]);
                k[j] = fmaf(xi, sWk[h * C * C + i * C + j], k[j]);
            }
        }
        float* qp = g_q + (n * NH + h) * C;
        float* kp = g_k + (n * NH + h) * C;
#pragma unroll
        for (int j = 0; j < C; j++) { qp[j] = q[j]; kp[j] = k[j]; }
    }
}

// ---------------- kernel 2: edge logits + segment max, plus u-vector blocks -
__global__ void __launch_bounds__(256)
k_edge_logit(const float* __restrict__ pos,
             const int* __restrict__ ei,
             const float* __restrict__ Wo) {
    int tid = threadIdx.x;

    if (blockIdx.x >= EL_BLOCKS) {
        // ---- u-vector blocks: u0/u1 per (node, head) for the fast path ----
        __shared__ float sWo[NH * C * C2];   // li=0 slice [h][c][j]
        for (int i = tid; i < NH * C * C2; i += blockDim.x) {
            int h = i / (C * C2);
            int r = i % (C * C2);
            sWo[i] = Wo[h * 3 * C * C2 + r];
        }
        __syncthreads();
        if (!g_fast) return;
        int n = (blockIdx.x - EL_BLOCKS) * blockDim.x + tid;
        if (n >= N_NODES) return;
        float x[C];
        {
            const float4* xp = (const float4*)(g_x + n * C);
#pragma unroll
            for (int i4 = 0; i4 < 4; i4++) {
                float4 v = xp[i4];
                x[i4 * 4 + 0] = v.x; x[i4 * 4 + 1] = v.y;
                x[i4 * 4 + 2] = v.z; x[i4 * 4 + 3] = v.w;
            }
        }
#pragma unroll
        for (int h = 0; h < NH; h++) {
            const float* S0r = &g_S0[h][HID][0];
            const float* S1r = &g_S1[h][HID][0];
            float u0[C2], u1[C2];
#pragma unroll
            for (int j = 0; j < C2; j++) { u0[j] = 0.f; u1[j] = 0.f; }
#pragma unroll
            for (int c = 0; c < C; c++) {
                float xc = x[c];
                float s0 = __ldg(S0r + c) * xc;
                float s1 = __ldg(S1r + c) * xc;
                const float* wo = sWo + h * C * C2 + c * C2;
#pragma unroll
                for (int j = 0; j < C2; j++) {
                    u0[j] = fmaf(s0, wo[j], u0[j]);
                    u1[j] = fmaf(s1, wo[j], u1[j]);
                }
            }
            float4* up = (float4*)(g_u + (n * NH + h) * 16);
            up[0] = make_float4(u0[0], u0[1], u0[2], u0[3]);
            up[1] = make_float4(u0[4], u0[5], u0[6], u0[7]);
            up[2] = make_float4(u1[0], u1[1], u1[2], u1[3]);
            up[3] = make_float4(u1[4], u1[5], u1[6], u1[7]);
        }
        return;
    }

    // ---- edge blocks ----
    int i = blockIdx.x * blockDim.x + tid;
    if (i >= E_HALF) return;

    int fast = g_fast;
    float fA0[NH], fA1[NH];
    if (fast) {
#pragma unroll
        for (int h = 0; h < NH; h++) { fA0[h] = g_A0[h][HID]; fA1[h] = g_A1[h][HID]; }
    }

    int e[2]  = { i, i + E_HALF };
    int s[2], t[2];
#pragma unroll
    for (int u = 0; u < 2; u++) { s[u] = ei[e[u]]; t[u] = ei[N_EDGES + e[u]]; }

    float d[2], d2i[2];
#pragma unroll
    for (int u = 0; u < 2; u++) {
        float dx = pos[3 * t[u] + 0] - pos[3 * s[u] + 0];
        float dy = pos[3 * t[u] + 1] - pos[3 * s[u] + 1];
        float dz = pos[3 * t[u] + 2] - pos[3 * s[u] + 2];
        float d2 = dx * dx + dy * dy + dz * dz;
        d[u]   = sqrtf(d2);
        d2i[u] = 1.0f / d2;
    }

#pragma unroll
    for (int u = 0; u < 2; u++) {
        float df_h[NH] = { d[u], d2i[u] };
        float lg_h[NH];
        int   ix_h[NH];
#pragma unroll
        for (int h = 0; h < NH; h++) {
            float df = df_h[h];
            float ab;
            int idx;
            if (fast) {
                idx = HID;
                ab  = fmaf(df, fA1[h], fA0[h]);
            } else {
                idx = bsearch64g(&g_t[h][0], df);
                ab  = fmaf(df, __ldg(&g_A1[h][idx]), __ldg(&g_A0[h][idx]));
            }

            const float4* qt = (const float4*)(g_q + (t[u] * NH + h) * C);
            const float4* ks = (const float4*)(g_k + (s[u] * NH + h) * C);
            float dot = 0.f;
#pragma unroll
            for (int i4 = 0; i4 < 4; i4++) {
                float4 a = qt[i4], b = ks[i4];
                dot += a.x * b.x + a.y * b.y + a.z * b.z + a.w * b.w;
            }
            float lg = fmaf(dot, 0.25f, ab);   // 1/sqrt(C) = 0.25
            lg_h[h] = lg;
            ix_h[h] = idx;
            atomicMax(&g_m[t[u] * NH + h], fenc(lg));
        }
        unsigned ixpack = (unsigned)ix_h[0] | ((unsigned)ix_h[1] << 8);
        g_edat[e[u]] = make_float4(d[u], lg_h[0], lg_h[1], __uint_as_float(ixpack));
        g_st[e[u]]   = (unsigned)s[u] | ((unsigned)t[u] << 16);
    }
}

// ---------------- kernel 3: exp + projected message accumulate --------------
__global__ void __launch_bounds__(256)
k_edge_acc(const float* __restrict__ Wo) {
    int i = blockIdx.x * blockDim.x + threadIdx.x;
    if (i >= E_HALF) return;
    int fast = g_fast;
    int e[2] = { i, i + E_HALF };

    if (fast) {
#pragma unroll
        for (int u = 0; u < 2; u++) {
            unsigned stp = g_st[e[u]];
            int s = (int)(stp & 0xffffu);
            int t = (int)(stp >> 16);

            float4 ed = g_edat[e[u]];
            float dd = ed.x;
            float df_h[NH] = { dd, 1.0f / (dd * dd) };

            uint2  m2  = *(const uint2*)(g_m + t * NH);
            float lg_h[NH] = { ed.y, ed.z };
            float m_h [NH] = { fdec(m2.x), fdec(m2.y) };

            const float4* up = (const float4*)(g_u + s * NH * 16);
#pragma unroll
            for (int h = 0; h < NH; h++) {
                float ex = __expf(lg_h[h] - m_h[h]);
                red_f(&g_z[t * NH + h], ex);
                float df = df_h[h];
                float4 u0l = up[h * 4 + 0], u0h = up[h * 4 + 1];
                float4 u1l = up[h * 4 + 2], u1h = up[h * 4 + 3];
                float4 plo, phi;
                plo.x = ex * fmaf(df, u1l.x, u0l.x);
                plo.y = ex * fmaf(df, u1l.y, u0l.y);
                plo.z = ex * fmaf(df, u1l.z, u0l.z);
                plo.w = ex * fmaf(df, u1l.w, u0l.w);
                phi.x = ex * fmaf(df, u1h.x, u0h.x);
                phi.y = ex * fmaf(df, u1h.y, u0h.y);
                phi.z = ex * fmaf(df, u1h.z, u0h.z);
                phi.w = ex * fmaf(df, u1h.w, u0h.w);
                float* accp = g_accp + (t * NH + h) * C2;
                red_v4(accp,     plo);
                red_v4(accp + 4, phi);
            }
        }
        return;
    }

    // ---- general slow path (tables from global; unused for this dataset) ----
#pragma unroll
    for (int u = 0; u < 2; u++) {
        unsigned stp = g_st[e[u]];
        int s = (int)(stp & 0xffffu);
        int t = (int)(stp >> 16);

        float4 ed = g_edat[e[u]];
        float dd = ed.x;
        unsigned ixpack = __float_as_uint(ed.w);

        float xs[C];
        {
            const float4* xp = (const float4*)(g_x + s * C);
#pragma unroll
            for (int i4 = 0; i4 < 4; i4++) {
                float4 v = xp[i4];
                xs[i4 * 4 + 0] = v.x; xs[i4 * 4 + 1] = v.y;
                xs[i4 * 4 + 2] = v.z; xs[i4 * 4 + 3] = v.w;
            }
        }
        float df_h[NH] = { dd, 1.0f / (dd * dd) };
        uint2  m2  = *(const uint2*)(g_m + t * NH);
        float lg_h[NH] = { ed.y, ed.z };
        float m_h [NH] = { fdec(m2.x), fdec(m2.y) };
        int   ix_h[NH] = { (int)(ixpack & 0xffu), (int)(ixpack >> 8) };

#pragma unroll
        for (int h = 0; h < NH; h++) {
            float ex = __expf(lg_h[h] - m_h[h]);
            red_f(&g_z[t * NH + h], ex);
            float df = df_h[h];
            const float* p0 = &g_S0[h][ix_h[h]][0];
            const float* p1 = &g_S1[h][ix_h[h]][0];
            float p[C2];
#pragma unroll
            for (int j = 0; j < C2; j++) p[j] = 0.f;
#pragma unroll
            for (int c = 0; c < C; c++) {
                float w = fmaf(df, __ldg(p1 + c), __ldg(p0 + c)) * xs[c];
                const float* wo = Wo + h * 3 * C * C2 + c * C2;
#pragma unroll
                for (int j = 0; j < C2; j++) p[j] = fmaf(w, __ldg(wo + j), p[j]);
            }
            float* accp = g_accp + (t * NH + h) * C2;
            red_v4(accp,     make_float4(ex * p[0], ex * p[1], ex * p[2], ex * p[3]));
            red_v4(accp + 4, make_float4(ex * p[4], ex * p[5], ex * p[6], ex * p[7]));
        }
    }
}

// ---------------- kernel 4: normalize + pool + fused final projection -------
__global__ void __launch_bounds__(256)
k_node_out(const int* __restrict__ batch,
           const float* __restrict__ Wproj,
           const float* __restrict__ bproj,
           float* __restrict__ out) {
    int tid  = threadIdx.x;
    int gi   = blockIdx.x * blockDim.x + tid;      // (n,h) pair index
    int lane = tid & 31;

    int n = gi >> 1;
    int h = gi & 1;
    bool valid = (gi < NO_THREADS);

    float v[C2];
#pragma unroll
    for (int j = 0; j < C2; j++) v[j] = 0.f;
    int g = 0;
    if (valid) {
        g = batch[n];
        float z = g_z[n * NH + h];
        if (z > 0.f) {
            float inv = 1.0f / z;
            const float4* ap = (const float4*)(g_accp + (n * NH + h) * C2);
            float4 a0 = ap[0], a1 = ap[1];
            v[0] = a0.x * inv; v[1] = a0.y * inv; v[2] = a0.z * inv; v[3] = a0.w * inv;
            v[4] = a1.x * inv; v[5] = a1.y * inv; v[6] = a1.z * inv; v[7] = a1.w * inv;
        }
    }

    int g0 = __shfl_sync(0xffffffffu, g, 0);
    bool uniform = __all_sync(0xffffffffu, valid && (g == g0));
    if (uniform) {
        // parity-preserving butterfly: each lane ends with its h-class total
#pragma unroll
        for (int j = 0; j < C2; j++) {
#pragma unroll
            for (int ofs = 16; ofs >= 2; ofs >>= 1)
                v[j] += __shfl_xor_sync(0xffffffffu, v[j], ofs);
        }
        if (lane < 2) {   // lane0: h=0 sums; lane1: h=1 sums
            float* dst = g_pooled + (g0 * NH + h) * C2;
            red_v4(dst,     make_float4(v[0], v[1], v[2], v[3]));
            red_v4(dst + 4, make_float4(v[4], v[5], v[6], v[7]));
        }
    } else if (valid) {
        // rotated per-lane REDs (bounded conflicts)
        float* dst = g_pooled + (g * NH + h) * C2;
#pragma unroll
        for (int jj = 0; jj < C2; jj++) {
            int j = (jj + lane) & (C2 - 1);
            red_f(dst + j, v[j]);
        }
    }

    // ---- last-block-done: fused final projection ----
    __shared__ int s_last;
    __threadfence();
    if (tid == 0) {
        int done = atomicAdd(&g_cnt, 1);
        s_last = (done == NO_BLOCKS - 1);
    }
    __syncthreads();
    if (s_last) {
        __threadfence();
#pragma unroll
        for (int r = 0; r < 2; r++) {
            int idx = tid + r * 256;          // 512 outputs
            int gg = idx / F_OUT;
            int oo = idx % F_OUT;
            float acc = bproj[oo];
#pragma unroll
            for (int t2 = 0; t2 < NH * C2; t2++)
                acc = fmaf(g_pooled[gg * (NH * C2) + t2], Wproj[t2 * F_OUT + oo], acc);
            out[gg * F_OUT + oo] = acc;
        }
    }
}

// ---------------- launch ----------------------------------------------------
extern "C" void kernel_launch(void* const* d_in, const int* in_sizes, int n_in,
                              void* d_out, int out_size) {
    const float* NF    = (const float*)d_in[0];
    const float* pos   = (const float*)d_in[1];
    const float* We    = (const float*)d_in[2];
    const float* be    = (const float*)d_in[3];
    const float* Wq    = (const float*)d_in[4];
    const float* Wk    = (const float*)d_in[5];
    const float* W1    = (const float*)d_in[6];
    const float* b1    = (const float*)d_in[7];
    const float* Wa    = (const float*)d_in[8];
    const float* Wv    = (const float*)d_in[9];
    const float* Wo    = (const float*)d_in[10];
    const float* Wproj = (const float*)d_in[11];
    const float* bproj = (const float*)d_in[12];
    const int*   ei    = (const int*)d_in[13];
    const int*   batch = (const int*)d_in[14];
    float* out = (float*)d_out;

    k_nodes<<<NODE_BLOCKS + 1, 256>>>(NF, We, be, Wq, Wk, W1, b1, Wa, Wv);
    k_edge_logit<<<EL_BLOCKS + U_BLOCKS, 256>>>(pos, ei, Wo);
    k_edge_acc<<<(E_HALF + 255) / 256, 256>>>(Wo);
    k_node_out<<<NO_BLOCKS, 256>>>(batch, Wproj, bproj, out);
}